// round 1
// baseline (speedup 1.0000x reference)
#include <cuda_runtime.h>

typedef unsigned long long u64;
typedef unsigned int u32;

#define BATCH 4
#define LDIM 4800
#define SDIM 4800
#define CDIM 256
#define H0C 60
#define W0C 80
#define SIM_SCALE (1.0f/25.6f)   // 1/(C*TEMP) = 1/(256*0.1)

// output layout (float32, concatenated reference outputs)
#define OFF_MATCH 92160000u
#define OFF_SID   92179200u
#define OFF_MCONF 92198400u
#define OFF_MK0   92217600u
#define OFF_MK1   92227200u
#define TOTAL_OUT 92265600u

// scratch (no cudaMalloc allowed -> __device__ globals)
__device__ float g_sim[BATCH * LDIM * SDIM];     // 368.64 MB
__device__ float g_rowZ[BATCH * LDIM];
__device__ float g_colZ[BATCH * SDIM];
__device__ u32   g_colMax[BATCH * SDIM];

// ---------- packed f32x2 helpers (sm_103a FFMA2) ----------
__device__ __forceinline__ u64 pk2(float lo, float hi) {
    u64 r; asm("mov.b64 %0, {%1,%2};" : "=l"(r) : "f"(lo), "f"(hi)); return r;
}
__device__ __forceinline__ float2 upk2(u64 v) {
    float2 r; asm("mov.b64 {%0,%1}, %2;" : "=f"(r.x), "=f"(r.y) : "l"(v)); return r;
}
__device__ __forceinline__ void fma2(u64 &d, u64 a, u64 b) {
    asm("fma.rn.f32x2 %0, %1, %2, %0;" : "+l"(d) : "l"(a), "l"(b));
}

// ---------- K1: sim = scale * feat0 @ feat1^T  (NT GEMM, fp32) ----------
#define BM 128
#define BN 128
#define BK 32
#define ASTR 132

__global__ void __launch_bounds__(256, 2) gemm_kernel(
    const float* __restrict__ f0, const float* __restrict__ f1)
{
    __shared__ float As[BK * ASTR];
    __shared__ float Bs[BK * ASTR];
    const int b   = blockIdx.z;
    const int l0  = blockIdx.y * BM;
    const int s0  = blockIdx.x * BN;
    const int tid = threadIdx.x;
    const int tx  = tid & 15;       // 0..15 (col group)
    const int ty  = tid >> 4;       // 0..15 (row group)
    const int lrow = tid >> 3;      // 0..31
    const int lcol = (tid & 7) << 2;// 0,4,...,28

    const float* A  = f0 + (size_t)b * LDIM * CDIM;
    const float* Bp = f1 + (size_t)b * SDIM * CDIM;

    u64 acc[8][4] = {};

    for (int k0 = 0; k0 < CDIM; k0 += BK) {
        #pragma unroll
        for (int rr = 0; rr < 4; rr++) {
            int row = lrow + rr * 32;
            int gl = l0 + row; if (gl > LDIM - 1) gl = LDIM - 1;
            float4 va = *(const float4*)(A + (size_t)gl * CDIM + k0 + lcol);
            As[(lcol + 0) * ASTR + row] = va.x;
            As[(lcol + 1) * ASTR + row] = va.y;
            As[(lcol + 2) * ASTR + row] = va.z;
            As[(lcol + 3) * ASTR + row] = va.w;
            int gs = s0 + row; if (gs > SDIM - 1) gs = SDIM - 1;
            float4 vb = *(const float4*)(Bp + (size_t)gs * CDIM + k0 + lcol);
            Bs[(lcol + 0) * ASTR + row] = vb.x;
            Bs[(lcol + 1) * ASTR + row] = vb.y;
            Bs[(lcol + 2) * ASTR + row] = vb.z;
            Bs[(lcol + 3) * ASTR + row] = vb.w;
        }
        __syncthreads();
        #pragma unroll
        for (int k = 0; k < BK; k++) {
            const float4* ar = (const float4*)(As + k * ASTR + ty * 8);
            const float4* br = (const float4*)(Bs + k * ASTR + tx * 8);
            float4 a0 = ar[0], a1 = ar[1];
            float4 b0 = br[0], b1 = br[1];
            u64 bv[4] = { pk2(b0.x, b0.y), pk2(b0.z, b0.w),
                          pk2(b1.x, b1.y), pk2(b1.z, b1.w) };
            float av[8] = { a0.x, a0.y, a0.z, a0.w, a1.x, a1.y, a1.z, a1.w };
            #pragma unroll
            for (int i = 0; i < 8; i++) {
                u64 ad = pk2(av[i], av[i]);
                #pragma unroll
                for (int j = 0; j < 4; j++) fma2(acc[i][j], ad, bv[j]);
            }
        }
        __syncthreads();
    }

    float* out = g_sim + (size_t)b * LDIM * SDIM;
    #pragma unroll
    for (int i = 0; i < 8; i++) {
        int gl = l0 + ty * 8 + i;
        if (gl >= LDIM) continue;
        float* orow = out + (size_t)gl * SDIM;
        #pragma unroll
        for (int j = 0; j < 4; j++) {
            int gs = s0 + tx * 8 + j * 2;
            if (gs < SDIM) {   // gs even, SDIM even -> gs+1 also in range
                float2 v = upk2(acc[i][j]);
                v.x *= SIM_SCALE; v.y *= SIM_SCALE;
                *(float2*)(orow + gs) = v;
            }
        }
    }
}

// ---------- K2: rowZ[b,l] = sum_s exp(sim), colZ[b,s] = sum_l exp(sim) ----------
#define NSLOT 19   // ceil(4800/256)
#define LCH 64

__global__ void __launch_bounds__(256) sums_kernel()
{
    const int b   = blockIdx.y;
    const int lc  = blockIdx.x;
    const int tid = threadIdx.x;
    const int lane = tid & 31;
    const float* simb = g_sim + (size_t)b * LDIM * SDIM;

    float colAcc[NSLOT];
    #pragma unroll
    for (int j = 0; j < NSLOT; j++) colAcc[j] = 0.f;

    for (int r = 0; r < LCH; r++) {
        int l = lc * LCH + r;
        const float* row = simb + (size_t)l * SDIM;
        float rs = 0.f;
        #pragma unroll
        for (int j = 0; j < NSLOT; j++) {
            int s = tid + (j << 8);
            if (s < SDIM) {
                float e = __expf(row[s]);
                rs += e;
                colAcc[j] += e;
            }
        }
        #pragma unroll
        for (int o = 16; o > 0; o >>= 1) rs += __shfl_xor_sync(0xffffffffu, rs, o);
        if (lane == 0) atomicAdd(&g_rowZ[b * LDIM + l], rs);
    }
    #pragma unroll
    for (int j = 0; j < NSLOT; j++) {
        int s = tid + (j << 8);
        if (s < SDIM) atomicAdd(&g_colZ[b * SDIM + s], colAcc[j]);
    }
}

// ---------- K3: conf = exp(2 sim)/(rowZ*colZ), write out, colMax(conf) ----------
__global__ void __launch_bounds__(256) conf_kernel(float* __restrict__ out)
{
    const int b   = blockIdx.y;
    const int lc  = blockIdx.x;
    const int tid = threadIdx.x;
    const float* simb = g_sim + (size_t)b * LDIM * SDIM;

    float colInv[NSLOT], colMax[NSLOT];
    #pragma unroll
    for (int j = 0; j < NSLOT; j++) {
        int s = tid + (j << 8);
        colInv[j] = (s < SDIM) ? 1.0f / g_colZ[b * SDIM + s] : 0.f;
        colMax[j] = 0.f;
    }
    for (int r = 0; r < LCH; r++) {
        int l = lc * LCH + r;
        float rowInv = 1.0f / g_rowZ[b * LDIM + l];
        const float* row = simb + (size_t)l * SDIM;
        float* orow = out + ((size_t)b * LDIM + l) * SDIM;
        #pragma unroll
        for (int j = 0; j < NSLOT; j++) {
            int s = tid + (j << 8);
            if (s < SDIM) {
                float c = __expf(2.0f * row[s]) * rowInv * colInv[j];
                orow[s] = c;
                colMax[j] = fmaxf(colMax[j], c);
            }
        }
    }
    #pragma unroll
    for (int j = 0; j < NSLOT; j++) {
        int s = tid + (j << 8);
        if (s < SDIM) atomicMax(&g_colMax[b * SDIM + s], __float_as_uint(colMax[j]));
    }
}

// ---------- K4: per-row threshold+border -> mutual-NN argmax + aux outputs ----------
__global__ void __launch_bounds__(256) match_kernel(float* __restrict__ out)
{
    const int bi  = blockIdx.x;          // b*L + l
    const int b   = bi / LDIM;
    const int l   = bi % LDIM;
    const int tid = threadIdx.x;
    __shared__ u64 sred[256];

    const float* crow = out + (size_t)bi * SDIM;  // conf at offset 0
    int lh = l / W0C, lw = l % W0C;
    bool lvalid = (lh >= 2) && (lh < H0C - 2) && (lw >= 2) && (lw < W0C - 2);

    u64 best = 0ull;
    if (lvalid) {
        for (int s = tid; s < SDIM; s += 256) {
            float c = crow[s];
            if (c > 0.2f) {
                int sh = s / W0C, sw = s % W0C;
                if (sh >= 2 && sh < H0C - 2 && sw >= 2 && sw < W0C - 2) {
                    // score = mask * rowmax * colmax: argmax over s == argmax of
                    // colmax among masked s (rowmax is a positive row constant).
                    // first-occurrence tie-break: pack ~s in the low word.
                    u64 key = ((u64)g_colMax[b * SDIM + s] << 32)
                            | (u64)(0xFFFFFFFFu - (u32)s);
                    if (key > best) best = key;
                }
            }
        }
    }
    sred[tid] = best;
    __syncthreads();
    for (int o = 128; o > 0; o >>= 1) {
        if (tid < o) { u64 v = sred[tid + o]; if (v > sred[tid]) sred[tid] = v; }
        __syncthreads();
    }
    if (tid == 0) {
        u64 bst = sred[0];
        float match = 0.f, sid = 0.f, mc = 0.f, kx = 0.f, ky = 0.f;
        if (bst) {
            int s = (int)(0xFFFFFFFFu - (u32)(bst & 0xFFFFFFFFull));
            match = 1.f;
            sid = (float)s;
            mc = crow[s];
            kx = (float)(s % W0C) * 8.f;
            ky = (float)(s / W0C) * 8.f;
        }
        out[OFF_MATCH + bi] = match;
        out[OFF_SID   + bi] = sid;
        out[OFF_MCONF + bi] = mc;
        size_t mk1 = (size_t)OFF_MK1 + (size_t)bi * 2;
        out[mk1]     = kx;
        out[mk1 + 1] = ky;
    }
}

// ---------- K0: zero accumulators; static mkpts0 ----------
__global__ void init_kernel(float* __restrict__ out, int full)
{
    int i = blockIdx.x * blockDim.x + threadIdx.x;
    if (i < BATCH * SDIM) { g_colZ[i] = 0.f; g_colMax[i] = 0u; }
    if (i < BATCH * LDIM) g_rowZ[i] = 0.f;
    if (full && i < LDIM) {
        out[OFF_MK0 + 2 * i]     = (float)(i % W0C) * 8.f;
        out[OFF_MK0 + 2 * i + 1] = (float)(i / W0C) * 8.f;
    }
}

extern "C" void kernel_launch(void* const* d_in, const int* in_sizes, int n_in,
                              void* d_out, int out_size)
{
    const float* f0 = (const float*)d_in[0];
    const float* f1 = (const float*)d_in[1];
    float* out = (float*)d_out;
    const bool full = ((unsigned)out_size >= TOTAL_OUT);

    init_kernel<<<(BATCH * SDIM + 255) / 256, 256>>>(out, full ? 1 : 0);

    dim3 gg((SDIM + BN - 1) / BN, (LDIM + BM - 1) / BM, BATCH);
    gemm_kernel<<<gg, 256>>>(f0, f1);

    dim3 gs(LDIM / LCH, BATCH);
    sums_kernel<<<gs, 256>>>();
    conf_kernel<<<gs, 256>>>(out);

    if (full) match_kernel<<<BATCH * LDIM, 256>>>(out);
}

// round 3
// speedup vs baseline: 1.8406x; 1.8406x over previous
#include <cuda_runtime.h>
#include <cuda_bf16.h>
#include <cstdint>

typedef unsigned long long u64;
typedef unsigned int u32;

#define BATCH 4
#define LDIM 4800
#define SDIM 4800
#define CDIM 256
#define KPK 768                         // packed K: [hi|hi|lo] x [hi|lo|hi]
#define EXP_SCALE (1.442695041f/25.6f)  // log2(e)/(C*TEMP): e^(dot/25.6) = 2^(dot*EXP_SCALE)

// output layout (float32, concatenated reference outputs)
#define OFF_MATCH 92160000u
#define OFF_SID   92179200u
#define OFF_MCONF 92198400u
#define OFF_MK0   92217600u
#define OFF_MK1   92227200u
#define TOTAL_OUT 92265600u

// ---------------- device scratch (no cudaMalloc allowed) ----------------
__device__ float g_sim[(size_t)BATCH * LDIM * SDIM];   // stores exp(sim)
__device__ __nv_bfloat16 g_a[(size_t)BATCH * LDIM * KPK];
__device__ __nv_bfloat16 g_b[(size_t)BATCH * SDIM * KPK];
__device__ float g_rowZ[BATCH * LDIM];
__device__ float g_colZ[BATCH * SDIM];
__device__ u32   g_colMax[BATCH * SDIM];
__device__ u32   g_mask[(size_t)BATCH * LDIM * 152];   // 150 words + 2 pad per row

// ---------------- helpers ----------------
__device__ __forceinline__ u32 smem_u32(const void* p) {
    u32 a;
    asm("{ .reg .u64 t; cvta.to.shared.u64 t, %1; cvt.u32.u64 %0, t; }"
        : "=r"(a) : "l"(p));
    return a;
}
__device__ __forceinline__ void cpasync16(u32 dst, const void* src) {
    asm volatile("cp.async.cg.shared.global [%0], [%1], 16;"
                 :: "r"(dst), "l"(src) : "memory");
}
#define CP_COMMIT() asm volatile("cp.async.commit_group;" ::: "memory")
#define CP_WAIT(n)  asm volatile("cp.async.wait_group %0;" :: "n"(n) : "memory")

__device__ __forceinline__ void ldsm4(u32& r0, u32& r1, u32& r2, u32& r3, u32 addr) {
    asm volatile("ldmatrix.sync.aligned.m8n8.x4.shared.b16 {%0,%1,%2,%3}, [%4];"
                 : "=r"(r0), "=r"(r1), "=r"(r2), "=r"(r3) : "r"(addr));
}
__device__ __forceinline__ void mma16816(float* d, const u32* a, const u32* b) {
    asm volatile(
        "mma.sync.aligned.m16n8k16.row.col.f32.bf16.bf16.f32 "
        "{%0,%1,%2,%3}, {%4,%5,%6,%7}, {%8,%9}, {%0,%1,%2,%3};"
        : "+f"(d[0]), "+f"(d[1]), "+f"(d[2]), "+f"(d[3])
        : "r"(a[0]), "r"(a[1]), "r"(a[2]), "r"(a[3]), "r"(b[0]), "r"(b[1]));
}
__device__ __forceinline__ float ex2f(float x) {
    float r; asm("ex2.approx.f32 %0, %1;" : "=f"(r) : "f"(x)); return r;
}

// ---------------- K_prep: fp32 -> bf16 hi/lo packed K=768 ----------------
__global__ void prep_kernel(const float* __restrict__ f0,
                            const float* __restrict__ f1)
{
    int idx = blockIdx.x * blockDim.x + threadIdx.x;
    const int TOT = BATCH * LDIM * CDIM;
    if (idx >= TOT) return;
    int row = idx >> 8;
    int c   = idx & 255;
    size_t base = (size_t)row * KPK;

    float x0 = f0[idx];
    __nv_bfloat16 h0 = __float2bfloat16(x0);
    __nv_bfloat16 l0 = __float2bfloat16(x0 - __bfloat162float(h0));
    g_a[base + c]       = h0;   // pairs with b hi
    g_a[base + 256 + c] = h0;   // pairs with b lo
    g_a[base + 512 + c] = l0;   // pairs with b hi

    float x1 = f1[idx];
    __nv_bfloat16 h1 = __float2bfloat16(x1);
    __nv_bfloat16 l1 = __float2bfloat16(x1 - __bfloat162float(h1));
    g_b[base + c]       = h1;
    g_b[base + 256 + c] = l1;
    g_b[base + 512 + c] = h1;
}

// ---------------- K_gemm: bf16 HMMA GEMM + fused exp / row / col sums ----------------
// CTA tile 128x128, 8 warps (2x4), warp tile 64x32, K=768 in 24 chunks of 32,
// cp.async double-buffered, padded 80B smem rows (conflict-free, no swizzle).
#define PADB 80
#define NCH  24

__global__ void __launch_bounds__(256, 2) gemm_kernel()
{
    __shared__ __align__(128) char smA[2][128 * PADB];
    __shared__ __align__(128) char smB[2][128 * PADB];

    const int tid  = threadIdx.x;
    const int wid  = tid >> 5;
    const int lane = tid & 31;
    const int b    = blockIdx.z;
    const int l0   = blockIdx.y * 128;
    const int s0   = blockIdx.x * 128;
    const int wm   = wid & 1;       // 2 warps over M
    const int wn   = wid >> 1;      // 4 warps over N

    const __nv_bfloat16* gA = g_a + (size_t)b * LDIM * KPK;
    const __nv_bfloat16* gB = g_b + (size_t)b * SDIM * KPK;
    u32 aA[2] = { smem_u32(smA[0]), smem_u32(smA[1]) };
    u32 aB[2] = { smem_u32(smB[0]), smem_u32(smB[1]) };

    // per-thread load slots: 512 16B-chunks per tile, 2 per thread per tile
    const int lrow0 = tid >> 2;          // 0..63
    const int lpart = tid & 3;           // 0..3

    float acc[4][4][4];
    #pragma unroll
    for (int i = 0; i < 4; i++)
        #pragma unroll
        for (int j = 0; j < 4; j++)
            #pragma unroll
            for (int v = 0; v < 4; v++) acc[i][j][v] = 0.f;

    auto load_chunk = [&](int ch, int buf) {
        #pragma unroll
        for (int i = 0; i < 2; i++) {
            int row = lrow0 + i * 64;
            u32 off = (u32)(row * PADB + lpart * 16);
            int gl = l0 + row; if (gl > LDIM - 1) gl = LDIM - 1;
            cpasync16(aA[buf] + off, gA + (size_t)gl * KPK + ch * 32 + lpart * 8);
            int gs = s0 + row; if (gs > SDIM - 1) gs = SDIM - 1;
            cpasync16(aB[buf] + off, gB + (size_t)gs * KPK + ch * 32 + lpart * 8);
        }
        CP_COMMIT();
    };

    load_chunk(0, 0);

    const int rsel = (lane & 7) + ((lane >> 3) & 1) * 8;  // matrix row within 16
    const int ksel = lane >> 4;                           // 0/1: k-halves

    #pragma unroll 1
    for (int ch = 0; ch < NCH; ch++) {
        if (ch < NCH - 1) { load_chunk(ch + 1, (ch + 1) & 1); CP_WAIT(1); }
        else              { CP_WAIT(0); }
        __syncthreads();
        u32 bufA = aA[ch & 1], bufB = aB[ch & 1];

        #pragma unroll
        for (int kk = 0; kk < 2; kk++) {
            u32 a[4][4], bb[4][2];
            #pragma unroll
            for (int mf = 0; mf < 4; mf++) {
                int row = wm * 64 + mf * 16 + rsel;
                ldsm4(a[mf][0], a[mf][1], a[mf][2], a[mf][3],
                      bufA + (u32)(row * PADB + kk * 32 + ksel * 16));
            }
            #pragma unroll
            for (int np = 0; np < 2; np++) {
                int row = wn * 32 + np * 16 + rsel;
                u32 r0, r1, r2, r3;
                ldsm4(r0, r1, r2, r3,
                      bufB + (u32)(row * PADB + kk * 32 + ksel * 16));
                bb[np * 2][0]     = r0; bb[np * 2][1]     = r2;
                bb[np * 2 + 1][0] = r1; bb[np * 2 + 1][1] = r3;
            }
            #pragma unroll
            for (int mf = 0; mf < 4; mf++)
                #pragma unroll
                for (int nf = 0; nf < 4; nf++)
                    mma16816(acc[mf][nf], a[mf], bb[nf]);
        }
        __syncthreads();
    }

    // ---- fused epilogue: e = exp(dot/25.6), store, row/col sums ----
    const int mrow0 = l0 + wm * 64;
    const int ncol0 = s0 + wn * 32;
    const int r_in  = lane >> 2;
    const int c_in  = (lane & 3) * 2;

    float rsum[4][2];
    float csum[4][2];
    #pragma unroll
    for (int i = 0; i < 4; i++) { rsum[i][0] = rsum[i][1] = 0.f; csum[i][0] = csum[i][1] = 0.f; }

    #pragma unroll
    for (int mf = 0; mf < 4; mf++) {
        #pragma unroll
        for (int half = 0; half < 2; half++) {
            int row = mrow0 + mf * 16 + half * 8 + r_in;
            bool rok = row < LDIM;
            float* orow = g_sim + ((size_t)b * LDIM + (rok ? row : 0)) * SDIM;
            #pragma unroll
            for (int nf = 0; nf < 4; nf++) {
                int col = ncol0 + nf * 8 + c_in;
                bool ok = rok && (col < SDIM);
                float e0 = ok ? ex2f(acc[mf][nf][half * 2]     * EXP_SCALE) : 0.f;
                float e1 = ok ? ex2f(acc[mf][nf][half * 2 + 1] * EXP_SCALE) : 0.f;
                if (ok) *(float2*)(orow + col) = make_float2(e0, e1);
                rsum[mf][half] += e0 + e1;
                csum[nf][0] += e0;
                csum[nf][1] += e1;
            }
        }
    }
    // row totals: reduce over lane&3
    #pragma unroll
    for (int mf = 0; mf < 4; mf++)
        #pragma unroll
        for (int half = 0; half < 2; half++) {
            float v = rsum[mf][half];
            v += __shfl_xor_sync(0xffffffffu, v, 1);
            v += __shfl_xor_sync(0xffffffffu, v, 2);
            if ((lane & 3) == 0) {
                int row = mrow0 + mf * 16 + half * 8 + r_in;
                if (row < LDIM) atomicAdd(&g_rowZ[b * LDIM + row], v);
            }
        }
    // col totals: reduce over lane>>2
    #pragma unroll
    for (int nf = 0; nf < 4; nf++)
        #pragma unroll
        for (int p = 0; p < 2; p++) {
            float v = csum[nf][p];
            v += __shfl_xor_sync(0xffffffffu, v, 4);
            v += __shfl_xor_sync(0xffffffffu, v, 8);
            v += __shfl_xor_sync(0xffffffffu, v, 16);
            if (lane < 4) {
                int col = ncol0 + nf * 8 + (lane & 3) * 2 + p;
                if (col < SDIM) atomicAdd(&g_colZ[b * SDIM + col], v);
            }
        }
}

// ---------------- K_conf: conf = e^2/(rowZ*colZ), colMax, candidate bitmask ----------------
#define NSLOT 19
#define LCH2 16
__global__ void __launch_bounds__(256) conf_kernel(float* __restrict__ out)
{
    const int b   = blockIdx.y;
    const int lc  = blockIdx.x;
    const int tid = threadIdx.x;

    float colInv[NSLOT], cmax[NSLOT];
    bool  bval[NSLOT];
    #pragma unroll
    for (int j = 0; j < NSLOT; j++) {
        int s = tid + (j << 8);
        if (s < SDIM) {
            colInv[j] = 1.0f / g_colZ[b * SDIM + s];
            int sh = s / 80, sw = s % 80;
            bval[j] = (sh >= 2) && (sh < 58) && (sw >= 2) && (sw < 78);
        } else { colInv[j] = 0.f; bval[j] = false; }
        cmax[j] = 0.f;
    }

    for (int r = 0; r < LCH2; r++) {
        int l  = lc * LCH2 + r;
        int bi = b * LDIM + l;
        float rowInv = 1.0f / g_rowZ[bi];
        int lh = l / 80, lw = l % 80;
        bool lval = (lh >= 2) && (lh < 58) && (lw >= 2) && (lw < 78);
        const float* erow = g_sim + (size_t)bi * SDIM;
        float* orow = out + (size_t)bi * SDIM;
        u32* mrow = g_mask + (size_t)bi * 152;
        #pragma unroll
        for (int j = 0; j < NSLOT; j++) {
            int s = tid + (j << 8);
            float c = 0.f;
            if (s < SDIM) {
                float e = erow[s];
                c = e * e * rowInv * colInv[j];
                orow[s] = c;
                cmax[j] = fmaxf(cmax[j], c);
            }
            u32 bits = __ballot_sync(0xffffffffu, (c > 0.2f) && bval[j] && lval);
            if ((tid & 31) == 0) {
                int w = (j << 3) + (tid >> 5);
                if (w < 152) mrow[w] = bits;
            }
        }
    }
    #pragma unroll
    for (int j = 0; j < NSLOT; j++) {
        int s = tid + (j << 8);
        if (s < SDIM)
            atomicMax(&g_colMax[b * SDIM + s], __float_as_uint(cmax[j]));
    }
}

// ---------------- K_match: one warp per row, scans candidate bitmask ----------------
__global__ void __launch_bounds__(256) match_kernel(float* __restrict__ out)
{
    const int wid  = threadIdx.x >> 5;
    const int lane = threadIdx.x & 31;
    const int bi   = blockIdx.x * 8 + wid;      // b*L + l
    const int b    = bi / LDIM;

    const u32* mrow = g_mask + (size_t)bi * 152;
    u64 best = 0ull;
    for (int w = lane; w < 150; w += 32) {
        u32 m = mrow[w];
        while (m) {
            int bit = __ffs(m) - 1;
            m &= m - 1;
            int s = (w << 5) + bit;
            // score argmax == argmax of colMax among masked s (rowmax is a
            // positive row constant); ~s low word -> first-occurrence ties.
            u64 key = ((u64)g_colMax[b * SDIM + s] << 32)
                    | (u64)(0xFFFFFFFFu - (u32)s);
            if (key > best) best = key;
        }
    }
    #pragma unroll
    for (int o = 16; o; o >>= 1) {
        u64 v = __shfl_xor_sync(0xffffffffu, best, o);
        if (v > best) best = v;
    }
    if (lane == 0) {
        float match = 0.f, sid = 0.f, mc = 0.f, kx = 0.f, ky = 0.f;
        if (best) {
            int s = (int)(0xFFFFFFFFu - (u32)(best & 0xFFFFFFFFull));
            match = 1.f;
            sid = (float)s;
            mc = out[(size_t)bi * SDIM + s];
            kx = (float)(s % 80) * 8.f;
            ky = (float)(s / 80) * 8.f;
        }
        out[OFF_MATCH + bi] = match;
        out[OFF_SID   + bi] = sid;
        out[OFF_MCONF + bi] = mc;
        out[OFF_MK1 + (size_t)bi * 2]     = kx;
        out[OFF_MK1 + (size_t)bi * 2 + 1] = ky;
    }
}

// ---------------- K_init: zero accumulators; static mkpts0 ----------------
__global__ void init_kernel(float* __restrict__ out, int full)
{
    int i = blockIdx.x * blockDim.x + threadIdx.x;
    if (i < BATCH * SDIM) { g_colZ[i] = 0.f; g_colMax[i] = 0u; }
    if (i < BATCH * LDIM) g_rowZ[i] = 0.f;
    if (full && i < LDIM) {
        out[OFF_MK0 + 2 * i]     = (float)(i % 80) * 8.f;
        out[OFF_MK0 + 2 * i + 1] = (float)(i / 80) * 8.f;
    }
}

extern "C" void kernel_launch(void* const* d_in, const int* in_sizes, int n_in,
                              void* d_out, int out_size)
{
    const float* f0 = (const float*)d_in[0];
    const float* f1 = (const float*)d_in[1];
    float* out = (float*)d_out;
    const bool full = ((unsigned)out_size >= TOTAL_OUT);

    init_kernel<<<(BATCH * SDIM + 255) / 256, 256>>>(out, full ? 1 : 0);

    const int TOT = BATCH * LDIM * CDIM;
    prep_kernel<<<(TOT + 255) / 256, 256>>>(f0, f1);

    dim3 gg((SDIM + 127) / 128, (LDIM + 127) / 128, BATCH);
    gemm_kernel<<<gg, 256>>>();

    dim3 gc(LDIM / LCH2, BATCH);
    conf_kernel<<<gc, 256>>>(out);

    if (full) match_kernel<<<(BATCH * LDIM) / 8, 256>>>(out);
}

// round 4
// speedup vs baseline: 2.9921x; 1.6256x over previous
#include <cuda_runtime.h>
#include <cuda_fp16.h>
#include <cstdint>

typedef unsigned long long u64;
typedef unsigned int u32;

#define BATCH 4
#define LDIM 4800
#define SDIM 4800
#define CDIM 256
#define KPK 512                         // packed K: A=[hi|lo], B=[hi|hi] (fp16)
#define EXP_SCALE (1.442695041f/25.6f)  // log2(e)/(C*TEMP)

// output layout (float32, concatenated reference outputs)
#define OFF_MATCH 92160000u
#define OFF_SID   92179200u
#define OFF_MCONF 92198400u
#define OFF_MK0   92217600u
#define OFF_MK1   92227200u
#define TOTAL_OUT 92265600u

// ---------------- device scratch ----------------
__device__ float g_sim[(size_t)BATCH * LDIM * SDIM];   // stores exp(sim)
__device__ __half g_a[(size_t)BATCH * LDIM * KPK];
__device__ __half g_b[(size_t)BATCH * SDIM * KPK];
__device__ float g_rowZ[BATCH * LDIM];
__device__ float g_colZ[BATCH * SDIM];
__device__ u32   g_colMax[BATCH * SDIM];
__device__ u32   g_mask[(size_t)BATCH * LDIM * 152];   // 150 words + pad per row

// ---------------- helpers ----------------
__device__ __forceinline__ u32 smem_u32(const void* p) {
    u32 a;
    asm("{ .reg .u64 t; cvta.to.shared.u64 t, %1; cvt.u32.u64 %0, t; }"
        : "=r"(a) : "l"(p));
    return a;
}
__device__ __forceinline__ void cpasync16(u32 dst, const void* src) {
    asm volatile("cp.async.cg.shared.global [%0], [%1], 16;"
                 :: "r"(dst), "l"(src) : "memory");
}
#define CP_COMMIT() asm volatile("cp.async.commit_group;" ::: "memory")
#define CP_WAIT(n)  asm volatile("cp.async.wait_group %0;" :: "n"(n) : "memory")

__device__ __forceinline__ void ldsm4(u32& r0, u32& r1, u32& r2, u32& r3, u32 addr) {
    asm volatile("ldmatrix.sync.aligned.m8n8.x4.shared.b16 {%0,%1,%2,%3}, [%4];"
                 : "=r"(r0), "=r"(r1), "=r"(r2), "=r"(r3) : "r"(addr));
}
__device__ __forceinline__ void mma16816(float* d, const u32* a, const u32* b) {
    asm volatile(
        "mma.sync.aligned.m16n8k16.row.col.f32.f16.f16.f32 "
        "{%0,%1,%2,%3}, {%4,%5,%6,%7}, {%8,%9}, {%0,%1,%2,%3};"
        : "+f"(d[0]), "+f"(d[1]), "+f"(d[2]), "+f"(d[3])
        : "r"(a[0]), "r"(a[1]), "r"(a[2]), "r"(a[3]), "r"(b[0]), "r"(b[1]));
}
__device__ __forceinline__ float ex2f(float x) {
    float r; asm("ex2.approx.f32 %0, %1;" : "=f"(r) : "f"(x)); return r;
}

// ---------------- K_prep: fp32 -> fp16 A=[hi|lo], B=[hi|hi] ----------------
__global__ void prep_kernel(const float* __restrict__ f0,
                            const float* __restrict__ f1)
{
    int idx = blockIdx.x * blockDim.x + threadIdx.x;
    const int TOT = BATCH * LDIM * CDIM;
    if (idx >= TOT) return;
    int row = idx >> 8;
    int c   = idx & 255;
    size_t base = (size_t)row * KPK;

    float x0 = f0[idx];
    __half h0 = __float2half(x0);
    __half l0 = __float2half(x0 - __half2float(h0));
    g_a[base + c]       = h0;
    g_a[base + 256 + c] = l0;

    __half h1 = __float2half(f1[idx]);
    g_b[base + c]       = h1;
    g_b[base + 256 + c] = h1;
}

// ---------------- K_gemm: fp16 HMMA GEMM + fused exp / row / col sums ----------------
// CTA tile 128x128, 8 warps (2x4), warp tile 64x32, K=512 in 16 chunks of 32,
// cp.async double-buffered, padded 80B smem rows (conflict-free).
#define PADB 80
#define NCH  16

__global__ void __launch_bounds__(256, 2) gemm_kernel()
{
    __shared__ __align__(128) char smA[2][128 * PADB];
    __shared__ __align__(128) char smB[2][128 * PADB];

    const int tid  = threadIdx.x;
    const int wid  = tid >> 5;
    const int lane = tid & 31;
    const int b    = blockIdx.z;
    const int l0   = blockIdx.y * 128;
    const int s0   = blockIdx.x * 128;
    const int wm   = wid & 1;
    const int wn   = wid >> 1;

    const __half* gA = g_a + (size_t)b * LDIM * KPK;
    const __half* gB = g_b + (size_t)b * SDIM * KPK;
    u32 aA[2] = { smem_u32(smA[0]), smem_u32(smA[1]) };
    u32 aB[2] = { smem_u32(smB[0]), smem_u32(smB[1]) };

    const int lrow0 = tid >> 2;
    const int lpart = tid & 3;

    float acc[4][4][4];
    #pragma unroll
    for (int i = 0; i < 4; i++)
        #pragma unroll
        for (int j = 0; j < 4; j++)
            #pragma unroll
            for (int v = 0; v < 4; v++) acc[i][j][v] = 0.f;

    auto load_chunk = [&](int ch, int buf) {
        #pragma unroll
        for (int i = 0; i < 2; i++) {
            int row = lrow0 + i * 64;
            u32 off = (u32)(row * PADB + lpart * 16);
            int gl = l0 + row; if (gl > LDIM - 1) gl = LDIM - 1;
            cpasync16(aA[buf] + off, gA + (size_t)gl * KPK + ch * 32 + lpart * 8);
            int gs = s0 + row; if (gs > SDIM - 1) gs = SDIM - 1;
            cpasync16(aB[buf] + off, gB + (size_t)gs * KPK + ch * 32 + lpart * 8);
        }
        CP_COMMIT();
    };

    load_chunk(0, 0);

    const int rsel = (lane & 7) + ((lane >> 3) & 1) * 8;
    const int ksel = lane >> 4;

    #pragma unroll 1
    for (int ch = 0; ch < NCH; ch++) {
        if (ch < NCH - 1) { load_chunk(ch + 1, (ch + 1) & 1); CP_WAIT(1); }
        else              { CP_WAIT(0); }
        __syncthreads();
        u32 bufA = aA[ch & 1], bufB = aB[ch & 1];

        #pragma unroll
        for (int kk = 0; kk < 2; kk++) {
            u32 a[4][4], bb[4][2];
            #pragma unroll
            for (int mf = 0; mf < 4; mf++) {
                int row = wm * 64 + mf * 16 + rsel;
                ldsm4(a[mf][0], a[mf][1], a[mf][2], a[mf][3],
                      bufA + (u32)(row * PADB + kk * 32 + ksel * 16));
            }
            #pragma unroll
            for (int np = 0; np < 2; np++) {
                int row = wn * 32 + np * 16 + rsel;
                u32 r0, r1, r2, r3;
                ldsm4(r0, r1, r2, r3,
                      bufB + (u32)(row * PADB + kk * 32 + ksel * 16));
                bb[np * 2][0]     = r0; bb[np * 2][1]     = r2;
                bb[np * 2 + 1][0] = r1; bb[np * 2 + 1][1] = r3;
            }
            #pragma unroll
            for (int mf = 0; mf < 4; mf++)
                #pragma unroll
                for (int nf = 0; nf < 4; nf++)
                    mma16816(acc[mf][nf], a[mf], bb[nf]);
        }
        __syncthreads();
    }

    // ---- fused epilogue: e = exp(dot/25.6), store, row/col sums ----
    const int mrow0 = l0 + wm * 64;
    const int ncol0 = s0 + wn * 32;
    const int r_in  = lane >> 2;
    const int c_in  = (lane & 3) * 2;

    float rsum[4][2];
    float csum[4][2];
    #pragma unroll
    for (int i = 0; i < 4; i++) { rsum[i][0] = rsum[i][1] = 0.f; csum[i][0] = csum[i][1] = 0.f; }

    #pragma unroll
    for (int mf = 0; mf < 4; mf++) {
        #pragma unroll
        for (int half = 0; half < 2; half++) {
            int row = mrow0 + mf * 16 + half * 8 + r_in;
            bool rok = row < LDIM;
            float* orow = g_sim + ((size_t)b * LDIM + (rok ? row : 0)) * SDIM;
            #pragma unroll
            for (int nf = 0; nf < 4; nf++) {
                int col = ncol0 + nf * 8 + c_in;
                bool ok = rok && (col < SDIM);
                float e0 = ok ? ex2f(acc[mf][nf][half * 2]     * EXP_SCALE) : 0.f;
                float e1 = ok ? ex2f(acc[mf][nf][half * 2 + 1] * EXP_SCALE) : 0.f;
                if (ok) *(float2*)(orow + col) = make_float2(e0, e1);
                rsum[mf][half] += e0 + e1;
                csum[nf][0] += e0;
                csum[nf][1] += e1;
            }
        }
    }
    #pragma unroll
    for (int mf = 0; mf < 4; mf++)
        #pragma unroll
        for (int half = 0; half < 2; half++) {
            float v = rsum[mf][half];
            v += __shfl_xor_sync(0xffffffffu, v, 1);
            v += __shfl_xor_sync(0xffffffffu, v, 2);
            if ((lane & 3) == 0) {
                int row = mrow0 + mf * 16 + half * 8 + r_in;
                if (row < LDIM) atomicAdd(&g_rowZ[b * LDIM + row], v);
            }
        }
    #pragma unroll
    for (int nf = 0; nf < 4; nf++)
        #pragma unroll
        for (int p = 0; p < 2; p++) {
            float v = csum[nf][p];
            v += __shfl_xor_sync(0xffffffffu, v, 4);
            v += __shfl_xor_sync(0xffffffffu, v, 8);
            v += __shfl_xor_sync(0xffffffffu, v, 16);
            if (lane < 4) {
                int col = ncol0 + nf * 8 + (lane & 3) * 2 + p;
                if (col < SDIM) atomicAdd(&g_colZ[b * SDIM + col], v);
            }
        }
}

// ---------------- K_conf: conf = e^2/(rowZ*colZ), colMax, candidate bitmask ----------------
// float4 everywhere, streaming loads/stores, 8 rows/block -> 2400 blocks.
#define CSLOT 5      // ceil(1200 float4 / 256 threads)
#define RPB 8
__global__ void __launch_bounds__(256) conf_kernel(float* __restrict__ out)
{
    const int b    = blockIdx.y;
    const int lc   = blockIdx.x;
    const int tid  = threadIdx.x;
    const int lane = tid & 31;

    float4 colInv[CSLOT], cmax[CSLOT];
    u32 bnib = 0;   // 4-bit border mask per slot
    #pragma unroll
    for (int j = 0; j < CSLOT; j++) {
        int s4 = tid + (j << 8);
        if (s4 < 1200) {
            colInv[j] = *(const float4*)(g_colZ + b * SDIM + s4 * 4);
            colInv[j].x = 1.f / colInv[j].x;
            colInv[j].y = 1.f / colInv[j].y;
            colInv[j].z = 1.f / colInv[j].z;
            colInv[j].w = 1.f / colInv[j].w;
            u32 nib = 0;
            #pragma unroll
            for (int k = 0; k < 4; k++) {
                int s = s4 * 4 + k;
                int sh = s / 80, sw = s % 80;
                if (sh >= 2 && sh < 58 && sw >= 2 && sw < 78) nib |= (1u << k);
            }
            bnib |= nib << (4 * j);
        } else {
            colInv[j] = make_float4(0.f, 0.f, 0.f, 0.f);
        }
        cmax[j] = make_float4(0.f, 0.f, 0.f, 0.f);
    }

    for (int r = 0; r < RPB; r++) {
        int l  = lc * RPB + r;
        int bi = b * LDIM + l;
        float rowInv = 1.0f / g_rowZ[bi];
        int lh = l / 80, lw = l % 80;
        bool lval = (lh >= 2) && (lh < 58) && (lw >= 2) && (lw < 78);
        const float4* erow = (const float4*)(g_sim + (size_t)bi * SDIM);
        float4* orow = (float4*)(out + (size_t)bi * SDIM);
        u32* mrow = g_mask + (size_t)bi * 152;
        #pragma unroll
        for (int j = 0; j < CSLOT; j++) {
            int s4 = tid + (j << 8);
            u32 nib = 0;
            if (s4 < 1200) {
                float4 e = __ldcs(erow + s4);
                float4 c;
                c.x = e.x * e.x * rowInv * colInv[j].x;
                c.y = e.y * e.y * rowInv * colInv[j].y;
                c.z = e.z * e.z * rowInv * colInv[j].z;
                c.w = e.w * e.w * rowInv * colInv[j].w;
                __stcs(orow + s4, c);
                cmax[j].x = fmaxf(cmax[j].x, c.x);
                cmax[j].y = fmaxf(cmax[j].y, c.y);
                cmax[j].z = fmaxf(cmax[j].z, c.z);
                cmax[j].w = fmaxf(cmax[j].w, c.w);
                if (lval) {
                    if (c.x > 0.2f) nib |= 1u;
                    if (c.y > 0.2f) nib |= 2u;
                    if (c.z > 0.2f) nib |= 4u;
                    if (c.w > 0.2f) nib |= 8u;
                    nib &= (bnib >> (4 * j)) & 15u;
                }
            }
            // combine 8 lanes' nibbles into one u32 covering 32 consecutive s
            u32 v = nib << ((lane & 7) * 4);
            v |= __shfl_xor_sync(0xffffffffu, v, 1);
            v |= __shfl_xor_sync(0xffffffffu, v, 2);
            v |= __shfl_xor_sync(0xffffffffu, v, 4);
            if ((lane & 7) == 0) {
                int w = (tid + (j << 8)) >> 3;   // s4/8
                if (w < 150) mrow[w] = v;
            }
        }
    }
    #pragma unroll
    for (int j = 0; j < CSLOT; j++) {
        int s4 = tid + (j << 8);
        if (s4 < 1200) {
            u32* cm = g_colMax + b * SDIM + s4 * 4;
            atomicMax(cm + 0, __float_as_uint(cmax[j].x));
            atomicMax(cm + 1, __float_as_uint(cmax[j].y));
            atomicMax(cm + 2, __float_as_uint(cmax[j].z));
            atomicMax(cm + 3, __float_as_uint(cmax[j].w));
        }
    }
}

// ---------------- K_match: one warp per row, scans candidate bitmask ----------------
__global__ void __launch_bounds__(256) match_kernel(float* __restrict__ out)
{
    const int wid  = threadIdx.x >> 5;
    const int lane = threadIdx.x & 31;
    const int bi   = blockIdx.x * 8 + wid;
    const int b    = bi / LDIM;

    const u32* mrow = g_mask + (size_t)bi * 152;
    u64 best = 0ull;
    for (int w = lane; w < 150; w += 32) {
        u32 m = mrow[w];
        while (m) {
            int bit = __ffs(m) - 1;
            m &= m - 1;
            int s = (w << 5) + bit;
            u64 key = ((u64)g_colMax[b * SDIM + s] << 32)
                    | (u64)(0xFFFFFFFFu - (u32)s);
            if (key > best) best = key;
        }
    }
    #pragma unroll
    for (int o = 16; o; o >>= 1) {
        u64 v = __shfl_xor_sync(0xffffffffu, best, o);
        if (v > best) best = v;
    }
    if (lane == 0) {
        float match = 0.f, sid = 0.f, mc = 0.f, kx = 0.f, ky = 0.f;
        if (best) {
            int s = (int)(0xFFFFFFFFu - (u32)(best & 0xFFFFFFFFull));
            match = 1.f;
            sid = (float)s;
            mc = out[(size_t)bi * SDIM + s];
            kx = (float)(s % 80) * 8.f;
            ky = (float)(s / 80) * 8.f;
        }
        out[OFF_MATCH + bi] = match;
        out[OFF_SID   + bi] = sid;
        out[OFF_MCONF + bi] = mc;
        out[OFF_MK1 + (size_t)bi * 2]     = kx;
        out[OFF_MK1 + (size_t)bi * 2 + 1] = ky;
    }
}

// ---------------- K_init ----------------
__global__ void init_kernel(float* __restrict__ out, int full)
{
    int i = blockIdx.x * blockDim.x + threadIdx.x;
    if (i < BATCH * SDIM) { g_colZ[i] = 0.f; g_colMax[i] = 0u; }
    if (i < BATCH * LDIM) g_rowZ[i] = 0.f;
    if (full && i < LDIM) {
        out[OFF_MK0 + 2 * i]     = (float)(i % 80) * 8.f;
        out[OFF_MK0 + 2 * i + 1] = (float)(i / 80) * 8.f;
    }
}

extern "C" void kernel_launch(void* const* d_in, const int* in_sizes, int n_in,
                              void* d_out, int out_size)
{
    const float* f0 = (const float*)d_in[0];
    const float* f1 = (const float*)d_in[1];
    float* out = (float*)d_out;
    const bool full = ((unsigned)out_size >= TOTAL_OUT);

    init_kernel<<<(BATCH * SDIM + 255) / 256, 256>>>(out, full ? 1 : 0);

    const int TOT = BATCH * LDIM * CDIM;
    prep_kernel<<<(TOT + 255) / 256, 256>>>(f0, f1);

    dim3 gg((SDIM + 127) / 128, (LDIM + 127) / 128, BATCH);
    gemm_kernel<<<gg, 256>>>();

    dim3 gc(LDIM / RPB, BATCH);
    conf_kernel<<<gc, 256>>>(out);

    if (full) match_kernel<<<(BATCH * LDIM) / 8, 256>>>(out);
}

// round 6
// speedup vs baseline: 4.3095x; 1.4403x over previous
#include <cuda_runtime.h>
#include <cuda_fp16.h>
#include <cstdint>
#include <cstring>

typedef unsigned long long u64;
typedef unsigned int u32;

#define BATCH 4
#define LDIM 4800
#define SDIM 4800
#define CDIM 256
#define KPK 256                         // plain fp16 both sides
#define EXP_SCALE (1.442695041f/25.6f)  // log2(e)/(C*TEMP)

// output layout (float32, concatenated reference outputs)
#define OFF_MATCH 92160000u
#define OFF_SID   92179200u
#define OFF_MCONF 92198400u
#define OFF_MK0   92217600u
#define OFF_MK1   92227200u
#define TOTAL_OUT 92265600u

// ---------------- device scratch ----------------
__device__ float g_sim[(size_t)BATCH * LDIM * SDIM];   // stores exp(sim)
__device__ __half g_a[(size_t)BATCH * LDIM * KPK];
__device__ __half g_b[(size_t)BATCH * SDIM * KPK];
__device__ float g_rowZ[BATCH * LDIM];
__device__ float g_colZ[BATCH * SDIM];
__device__ u32   g_colMax[BATCH * SDIM];
__device__ u32   g_mask[(size_t)BATCH * LDIM * 152];   // 150 words + pad per row

// ---------------- helpers ----------------
__device__ __forceinline__ u32 h2_bits(__half2 h) {
    u32 r; memcpy(&r, &h, 4); return r;
}
__device__ __forceinline__ u32 smem_u32(const void* p) {
    u32 a;
    asm("{ .reg .u64 t; cvta.to.shared.u64 t, %1; cvt.u32.u64 %0, t; }"
        : "=r"(a) : "l"(p));
    return a;
}
__device__ __forceinline__ void cpasync16(u32 dst, const void* src) {
    asm volatile("cp.async.cg.shared.global [%0], [%1], 16;"
                 :: "r"(dst), "l"(src) : "memory");
}
#define CP_COMMIT() asm volatile("cp.async.commit_group;" ::: "memory")
#define CP_WAIT(n)  asm volatile("cp.async.wait_group %0;" :: "n"(n) : "memory")

__device__ __forceinline__ void ldsm4(u32& r0, u32& r1, u32& r2, u32& r3, u32 addr) {
    asm volatile("ldmatrix.sync.aligned.m8n8.x4.shared.b16 {%0,%1,%2,%3}, [%4];"
                 : "=r"(r0), "=r"(r1), "=r"(r2), "=r"(r3) : "r"(addr));
}
__device__ __forceinline__ void mma16816(float* d, const u32* a, const u32* b) {
    asm volatile(
        "mma.sync.aligned.m16n8k16.row.col.f32.f16.f16.f32 "
        "{%0,%1,%2,%3}, {%4,%5,%6,%7}, {%8,%9}, {%0,%1,%2,%3};"
        : "+f"(d[0]), "+f"(d[1]), "+f"(d[2]), "+f"(d[3])
        : "r"(a[0]), "r"(a[1]), "r"(a[2]), "r"(a[3]), "r"(b[0]), "r"(b[1]));
}
__device__ __forceinline__ float ex2f(float x) {
    float r; asm("ex2.approx.f32 %0, %1;" : "=f"(r) : "f"(x)); return r;
}

// ---------------- K_prep: fp32 -> fp16 ----------------
__global__ void prep_kernel(const float* __restrict__ f0,
                            const float* __restrict__ f1)
{
    int idx = blockIdx.x * blockDim.x + threadIdx.x;
    const int TOT = (BATCH * LDIM * CDIM) / 4;
    if (idx >= TOT) return;
    float4 x0 = *(const float4*)(f0 + idx * 4);
    float4 x1 = *(const float4*)(f1 + idx * 4);
    u32 a01 = h2_bits(__floats2half2_rn(x0.x, x0.y));
    u32 a23 = h2_bits(__floats2half2_rn(x0.z, x0.w));
    u32 b01 = h2_bits(__floats2half2_rn(x1.x, x1.y));
    u32 b23 = h2_bits(__floats2half2_rn(x1.z, x1.w));
    *(uint2*)(g_a + idx * 4) = make_uint2(a01, a23);
    *(uint2*)(g_b + idx * 4) = make_uint2(b01, b23);
}

// ---------------- K_gemm: fp16 HMMA GEMM + fused exp / row / col sums ----------------
// CTA tile 128x128, 8 warps (2x4), warp tile 64x32, K=256 in 8 chunks of 32,
// cp.async double-buffered, padded 80B smem rows (conflict-free).
#define PADB 80
#define NCH  8

__global__ void __launch_bounds__(256, 2) gemm_kernel()
{
    __shared__ __align__(128) char smA[2][128 * PADB];
    __shared__ __align__(128) char smB[2][128 * PADB];

    const int tid  = threadIdx.x;
    const int wid  = tid >> 5;
    const int lane = tid & 31;
    const int b    = blockIdx.z;
    const int l0   = blockIdx.y * 128;
    const int s0   = blockIdx.x * 128;
    const int wm   = wid & 1;
    const int wn   = wid >> 1;

    const __half* gA = g_a + (size_t)b * LDIM * KPK;
    const __half* gB = g_b + (size_t)b * SDIM * KPK;
    u32 aA[2] = { smem_u32(smA[0]), smem_u32(smA[1]) };
    u32 aB[2] = { smem_u32(smB[0]), smem_u32(smB[1]) };

    const int lrow0 = tid >> 2;
    const int lpart = tid & 3;

    float acc[4][4][4];
    #pragma unroll
    for (int i = 0; i < 4; i++)
        #pragma unroll
        for (int j = 0; j < 4; j++)
            #pragma unroll
            for (int v = 0; v < 4; v++) acc[i][j][v] = 0.f;

    auto load_chunk = [&](int ch, int buf) {
        #pragma unroll
        for (int i = 0; i < 2; i++) {
            int row = lrow0 + i * 64;
            u32 off = (u32)(row * PADB + lpart * 16);
            int gl = l0 + row; if (gl > LDIM - 1) gl = LDIM - 1;
            cpasync16(aA[buf] + off, gA + (size_t)gl * KPK + ch * 32 + lpart * 8);
            int gs = s0 + row; if (gs > SDIM - 1) gs = SDIM - 1;
            cpasync16(aB[buf] + off, gB + (size_t)gs * KPK + ch * 32 + lpart * 8);
        }
        CP_COMMIT();
    };

    load_chunk(0, 0);

    const int rsel = (lane & 7) + ((lane >> 3) & 1) * 8;
    const int ksel = lane >> 4;

    #pragma unroll 1
    for (int ch = 0; ch < NCH; ch++) {
        if (ch < NCH - 1) { load_chunk(ch + 1, (ch + 1) & 1); CP_WAIT(1); }
        else              { CP_WAIT(0); }
        __syncthreads();
        u32 bufA = aA[ch & 1], bufB = aB[ch & 1];

        #pragma unroll
        for (int kk = 0; kk < 2; kk++) {
            u32 a[4][4], bb[4][2];
            #pragma unroll
            for (int mf = 0; mf < 4; mf++) {
                int row = wm * 64 + mf * 16 + rsel;
                ldsm4(a[mf][0], a[mf][1], a[mf][2], a[mf][3],
                      bufA + (u32)(row * PADB + kk * 32 + ksel * 16));
            }
            #pragma unroll
            for (int np = 0; np < 2; np++) {
                int row = wn * 32 + np * 16 + rsel;
                u32 r0, r1, r2, r3;
                ldsm4(r0, r1, r2, r3,
                      bufB + (u32)(row * PADB + kk * 32 + ksel * 16));
                bb[np * 2][0]     = r0; bb[np * 2][1]     = r2;
                bb[np * 2 + 1][0] = r1; bb[np * 2 + 1][1] = r3;
            }
            #pragma unroll
            for (int mf = 0; mf < 4; mf++)
                #pragma unroll
                for (int nf = 0; nf < 4; nf++)
                    mma16816(acc[mf][nf], a[mf], bb[nf]);
        }
        __syncthreads();
    }

    // ---- fused epilogue: e = exp(dot/25.6), store, row/col sums ----
    const int mrow0 = l0 + wm * 64;
    const int ncol0 = s0 + wn * 32;
    const int r_in  = lane >> 2;
    const int c_in  = (lane & 3) * 2;

    float rsum[4][2];
    float csum[4][2];
    #pragma unroll
    for (int i = 0; i < 4; i++) { rsum[i][0] = rsum[i][1] = 0.f; csum[i][0] = csum[i][1] = 0.f; }

    #pragma unroll
    for (int mf = 0; mf < 4; mf++) {
        #pragma unroll
        for (int half = 0; half < 2; half++) {
            int row = mrow0 + mf * 16 + half * 8 + r_in;
            bool rok = row < LDIM;
            float* orow = g_sim + ((size_t)b * LDIM + (rok ? row : 0)) * SDIM;
            #pragma unroll
            for (int nf = 0; nf < 4; nf++) {
                int col = ncol0 + nf * 8 + c_in;
                bool ok = rok && (col < SDIM);
                float e0 = ok ? ex2f(acc[mf][nf][half * 2]     * EXP_SCALE) : 0.f;
                float e1 = ok ? ex2f(acc[mf][nf][half * 2 + 1] * EXP_SCALE) : 0.f;
                if (ok) __stcs((float2*)(orow + col), make_float2(e0, e1));
                rsum[mf][half] += e0 + e1;
                csum[nf][0] += e0;
                csum[nf][1] += e1;
            }
        }
    }
    #pragma unroll
    for (int mf = 0; mf < 4; mf++)
        #pragma unroll
        for (int half = 0; half < 2; half++) {
            float v = rsum[mf][half];
            v += __shfl_xor_sync(0xffffffffu, v, 1);
            v += __shfl_xor_sync(0xffffffffu, v, 2);
            if ((lane & 3) == 0) {
                int row = mrow0 + mf * 16 + half * 8 + r_in;
                if (row < LDIM) atomicAdd(&g_rowZ[b * LDIM + row], v);
            }
        }
    #pragma unroll
    for (int nf = 0; nf < 4; nf++)
        #pragma unroll
        for (int p = 0; p < 2; p++) {
            float v = csum[nf][p];
            v += __shfl_xor_sync(0xffffffffu, v, 4);
            v += __shfl_xor_sync(0xffffffffu, v, 8);
            v += __shfl_xor_sync(0xffffffffu, v, 16);
            if (lane < 4) {
                int col = ncol0 + nf * 8 + (lane & 3) * 2 + p;
                if (col < SDIM) atomicAdd(&g_colZ[b * SDIM + col], v);
            }
        }
}

// ---------------- K_conf: conf = e^2/(rowZ*colZ), colMax, candidate bitmask ----------------
// float4 streaming, 512 threads, 3 slots, 8 rows/block -> 600x4 grid.
#define CSLOT 3
#define RPB 8
#define CTHREADS 512
__global__ void __launch_bounds__(CTHREADS) conf_kernel(float* __restrict__ out)
{
    const int b    = blockIdx.y;
    const int lc   = blockIdx.x;
    const int tid  = threadIdx.x;
    const int lane = tid & 31;

    float4 colInv[CSLOT], cmax[CSLOT];
    u32 bnib = 0;   // 4-bit border mask per slot
    #pragma unroll
    for (int j = 0; j < CSLOT; j++) {
        int s4 = tid + j * CTHREADS;
        if (s4 < 1200) {
            colInv[j] = *(const float4*)(g_colZ + b * SDIM + s4 * 4);
            colInv[j].x = 1.f / colInv[j].x;
            colInv[j].y = 1.f / colInv[j].y;
            colInv[j].z = 1.f / colInv[j].z;
            colInv[j].w = 1.f / colInv[j].w;
            u32 nib = 0;
            #pragma unroll
            for (int k = 0; k < 4; k++) {
                int s = s4 * 4 + k;
                int sh = s / 80, sw = s % 80;
                if (sh >= 2 && sh < 58 && sw >= 2 && sw < 78) nib |= (1u << k);
            }
            bnib |= nib << (4 * j);
        } else {
            colInv[j] = make_float4(0.f, 0.f, 0.f, 0.f);
        }
        cmax[j] = make_float4(0.f, 0.f, 0.f, 0.f);
    }

    for (int r = 0; r < RPB; r++) {
        int l  = lc * RPB + r;
        int bi = b * LDIM + l;
        float rowInv = 1.0f / g_rowZ[bi];
        int lh = l / 80, lw = l % 80;
        bool lval = (lh >= 2) && (lh < 58) && (lw >= 2) && (lw < 78);
        const float4* erow = (const float4*)(g_sim + (size_t)bi * SDIM);
        float4* orow = (float4*)(out + (size_t)bi * SDIM);
        u32* mrow = g_mask + (size_t)bi * 152;
        #pragma unroll
        for (int j = 0; j < CSLOT; j++) {
            int s4 = tid + j * CTHREADS;
            u32 nib = 0;
            if (s4 < 1200) {
                float4 e = __ldcs(erow + s4);
                float4 c;
                c.x = e.x * e.x * rowInv * colInv[j].x;
                c.y = e.y * e.y * rowInv * colInv[j].y;
                c.z = e.z * e.z * rowInv * colInv[j].z;
                c.w = e.w * e.w * rowInv * colInv[j].w;
                __stcs(orow + s4, c);
                cmax[j].x = fmaxf(cmax[j].x, c.x);
                cmax[j].y = fmaxf(cmax[j].y, c.y);
                cmax[j].z = fmaxf(cmax[j].z, c.z);
                cmax[j].w = fmaxf(cmax[j].w, c.w);
                if (lval) {
                    if (c.x > 0.2f) nib |= 1u;
                    if (c.y > 0.2f) nib |= 2u;
                    if (c.z > 0.2f) nib |= 4u;
                    if (c.w > 0.2f) nib |= 8u;
                    nib &= (bnib >> (4 * j)) & 15u;
                }
            }
            u32 v = nib << ((lane & 7) * 4);
            v |= __shfl_xor_sync(0xffffffffu, v, 1);
            v |= __shfl_xor_sync(0xffffffffu, v, 2);
            v |= __shfl_xor_sync(0xffffffffu, v, 4);
            if ((lane & 7) == 0) {
                int w = (tid + j * CTHREADS) >> 3;
                if (w < 150 && (tid + j * CTHREADS) < 1200) mrow[w] = v;
            }
        }
    }
    #pragma unroll
    for (int j = 0; j < CSLOT; j++) {
        int s4 = tid + j * CTHREADS;
        if (s4 < 1200) {
            u32* cm = g_colMax + b * SDIM + s4 * 4;
            atomicMax(cm + 0, __float_as_uint(cmax[j].x));
            atomicMax(cm + 1, __float_as_uint(cmax[j].y));
            atomicMax(cm + 2, __float_as_uint(cmax[j].z));
            atomicMax(cm + 3, __float_as_uint(cmax[j].w));
        }
    }
}

// ---------------- K_match: one warp per row, scans candidate bitmask ----------------
__global__ void __launch_bounds__(256) match_kernel(float* __restrict__ out)
{
    const int wid  = threadIdx.x >> 5;
    const int lane = threadIdx.x & 31;
    const int bi   = blockIdx.x * 8 + wid;
    const int b    = bi / LDIM;

    const u32* mrow = g_mask + (size_t)bi * 152;
    u64 best = 0ull;
    for (int w = lane; w < 150; w += 32) {
        u32 m = mrow[w];
        while (m) {
            int bit = __ffs(m) - 1;
            m &= m - 1;
            int s = (w << 5) + bit;
            u64 key = ((u64)g_colMax[b * SDIM + s] << 32)
                    | (u64)(0xFFFFFFFFu - (u32)s);
            if (key > best) best = key;
        }
    }
    #pragma unroll
    for (int o = 16; o; o >>= 1) {
        u64 v = __shfl_xor_sync(0xffffffffu, best, o);
        if (v > best) best = v;
    }
    if (lane == 0) {
        float match = 0.f, sid = 0.f, mc = 0.f, kx = 0.f, ky = 0.f;
        if (best) {
            int s = (int)(0xFFFFFFFFu - (u32)(best & 0xFFFFFFFFull));
            match = 1.f;
            sid = (float)s;
            mc = out[(size_t)bi * SDIM + s];
            kx = (float)(s % 80) * 8.f;
            ky = (float)(s / 80) * 8.f;
        }
        out[OFF_MATCH + bi] = match;
        out[OFF_SID   + bi] = sid;
        out[OFF_MCONF + bi] = mc;
        out[OFF_MK1 + (size_t)bi * 2]     = kx;
        out[OFF_MK1 + (size_t)bi * 2 + 1] = ky;
    }
}

// ---------------- K_init ----------------
__global__ void init_kernel(float* __restrict__ out, int full)
{
    int i = blockIdx.x * blockDim.x + threadIdx.x;
    if (i < BATCH * SDIM) { g_colZ[i] = 0.f; g_colMax[i] = 0u; }
    if (i < BATCH * LDIM) g_rowZ[i] = 0.f;
    if (full && i < LDIM) {
        out[OFF_MK0 + 2 * i]     = (float)(i % 80) * 8.f;
        out[OFF_MK0 + 2 * i + 1] = (float)(i / 80) * 8.f;
    }
}

extern "C" void kernel_launch(void* const* d_in, const int* in_sizes, int n_in,
                              void* d_out, int out_size)
{
    const float* f0 = (const float*)d_in[0];
    const float* f1 = (const float*)d_in[1];
    float* out = (float*)d_out;
    const bool full = ((unsigned)out_size >= TOTAL_OUT);

    init_kernel<<<(BATCH * SDIM + 255) / 256, 256>>>(out, full ? 1 : 0);

    const int TOT = (BATCH * LDIM * CDIM) / 4;
    prep_kernel<<<(TOT + 255) / 256, 256>>>(f0, f1);

    dim3 gg((SDIM + 127) / 128, (LDIM + 127) / 128, BATCH);
    gemm_kernel<<<gg, 256>>>();

    dim3 gc(LDIM / RPB, BATCH);
    conf_kernel<<<gc, CTHREADS>>>(out);

    if (full) match_kernel<<<(BATCH * LDIM) / 8, 256>>>(out);
}